// round 8
// baseline (speedup 1.0000x reference)
#include <cuda_runtime.h>
#include <cstdint>

#define B_    4
#define T_    1024
#define DIM_  512
#define POOL_ 64
#define K_    50
#define TK_   2      // tokens per block

// Scratch (device globals: allocation-free per harness rules)
__device__ __align__(16) float g_y[B_ * POOL_ * POOL_];   // y[b][t<64][p]
__device__ __align__(16) float g_z[B_ * POOL_ * DIM_];    // z[b][j][d]

// packed fp32x2 ops (Blackwell FFMA2 — only reachable via PTX)
#define FMA2(d, a, b) \
    asm("fma.rn.f32x2 %0, %1, %2, %3;" : "=l"(d) : "l"(a), "l"(b), "l"(d))
#define ADD2(d, a, b) \
    asm("add.rn.f32x2 %0, %1, %2;" : "=l"(d) : "l"(a), "l"(b))
#define UNPACK2(lo, hi, v) \
    asm("mov.b64 {%0, %1}, %2;" : "=f"(lo), "=f"(hi) : "l"(v))
#define LDS_V2U64(a0, a1, addr) \
    asm("ld.shared.v2.b64 {%0, %1}, [%2];" : "=l"(a0), "=l"(a1) : "r"(addr))

// ---------------------------------------------------------------------------
// Shared GEMM+LN stage (device inline): computes yv[b] (LN'd pool outputs)
// for token pair t0,t0+1; result for thread tid<128: (tk=tid>>6, pp=tid&63).
// Layout identical to round-7 kernel. Returns vv via yv[], ysum via *ysum.
// ---------------------------------------------------------------------------
struct K1Smem {
    float2 pool2[B_ * TK_ * DIM_];     // 32KB: dup x, then partials (reuse)
    float  sv[TK_ * POOL_];
    float  wsum[4][B_], wsq[4][B_];
    int    sidx[TK_][POOL_];           // top-50 indices per token
};

__device__ __forceinline__ void stage1_gemm_ln(
        K1Smem* sm, int t0, int tid,
        const float* __restrict__ x,  const float* __restrict__ w1,
        const float* __restrict__ b1, const float* __restrict__ g1,
        const float* __restrict__ bt1,
        float yv[B_], float* ysum_out) {
    float* poolf = reinterpret_cast<float*>(sm->pool2);
    const int pg = tid & 15;
    const int dc = tid >> 4;

    uint32_t sx;
    asm("{ .reg .u64 t; cvta.to.shared.u64 t, %1; cvt.u32.u64 %0, t; }"
        : "=r"(sx) : "l"(sm->pool2));

    // phase 1: load x rows, lane-duplicated
    #pragma unroll
    for (int i = tid; i < B_ * (DIM_ / 4); i += 256) {
        int b = i >> 7, j = i & 127;
        const float* xb = x + ((size_t)b * T_ + t0) * DIM_;
        float4 v0 = reinterpret_cast<const float4*>(xb)[j];
        float4 v1 = reinterpret_cast<const float4*>(xb + DIM_)[j];
        float2* d0 = sm->pool2 + (b * 2 + 0) * DIM_ + j * 4;
        d0[0] = make_float2(v0.x, v0.x);
        d0[1] = make_float2(v0.y, v0.y);
        d0[2] = make_float2(v0.z, v0.z);
        d0[3] = make_float2(v0.w, v0.w);
        float2* d1 = sm->pool2 + (b * 2 + 1) * DIM_ + j * 4;
        d1[0] = make_float2(v1.x, v1.x);
        d1[1] = make_float2(v1.y, v1.y);
        d1[2] = make_float2(v1.z, v1.z);
        d1[3] = make_float2(v1.w, v1.w);
    }
    __syncthreads();

    // main loop: 32 dims x 8 (b,tok) rows x 2 pool-pairs
    unsigned long long acc[8][2] = {};
    const ulonglong2* w1q = reinterpret_cast<const ulonglong2*>(w1);

    #pragma unroll 4
    for (int d2 = 0; d2 < 16; d2++) {
        const int d = dc * 32 + d2 * 2;
        ulonglong2 wd0 = __ldg(w1q + (size_t)d * 16 + pg);
        ulonglong2 wd1 = __ldg(w1q + (size_t)(d + 1) * 16 + pg);
        #pragma unroll
        for (int bt = 0; bt < 8; bt++) {
            unsigned long long xv0, xv1;
            LDS_V2U64(xv0, xv1, sx + (uint32_t)((bt * DIM_ + d) * 8));
            FMA2(acc[bt][0], xv0, wd0.x);
            FMA2(acc[bt][1], xv0, wd0.y);
            FMA2(acc[bt][0], xv1, wd1.x);
            FMA2(acc[bt][1], xv1, wd1.y);
        }
    }

    // reduce over dc: butterfly (dc pairs), then smem
    #pragma unroll
    for (int bt = 0; bt < 8; bt++) {
        #pragma unroll
        for (int pr = 0; pr < 2; pr++) {
            unsigned long long o = __shfl_xor_sync(0xffffffffu, acc[bt][pr], 16);
            ADD2(acc[bt][pr], acc[bt][pr], o);
        }
    }
    __syncthreads();

    if ((tid & 16) == 0) {
        const int w = tid >> 5;
        #pragma unroll
        for (int bt = 0; bt < 8; bt++) {
            #pragma unroll
            for (int pr = 0; pr < 2; pr++) {
                float lo, hi;
                UNPACK2(lo, hi, acc[bt][pr]);
                poolf[w * 512 + bt * 64 + pg * 4 + pr * 2 + 0] = lo;
                poolf[w * 512 + bt * 64 + pg * 4 + pr * 2 + 1] = hi;
            }
        }
    }
    __syncthreads();

    // LN tail on first 128 threads
    float vv[B_];
    if (tid < TK_ * POOL_) {
        const int tk = tid >> 6;
        const int pp = tid & 63;
        const float bias = b1[pp];
        #pragma unroll
        for (int b = 0; b < B_; b++) {
            float a = bias;
            #pragma unroll
            for (int w = 0; w < 8; w++)
                a += poolf[w * 512 + (b * TK_ + tk) * 64 + pp];
            vv[b] = fmaxf(a, 0.f);
        }
        float s[B_], q[B_];
        #pragma unroll
        for (int b = 0; b < B_; b++) { s[b] = vv[b]; q[b] = vv[b] * vv[b]; }
        #pragma unroll
        for (int off = 16; off > 0; off >>= 1) {
            #pragma unroll
            for (int b = 0; b < B_; b++) {
                s[b] += __shfl_xor_sync(0xffffffffu, s[b], off);
                q[b] += __shfl_xor_sync(0xffffffffu, q[b], off);
            }
        }
        const int w = tid >> 5;
        if ((tid & 31) == 0) {
            #pragma unroll
            for (int b = 0; b < B_; b++) { sm->wsum[w][b] = s[b]; sm->wsq[w][b] = q[b]; }
        }
    }
    __syncthreads();

    float ysum = 0.f;
    if (tid < TK_ * POOL_) {
        const int tk = tid >> 6;
        const int pp = tid & 63;
        const float gp = g1[pp], bp = bt1[pp];
        #pragma unroll
        for (int b = 0; b < B_; b++) {
            float S = sm->wsum[tk * 2][b] + sm->wsum[tk * 2 + 1][b];
            float Q = sm->wsq[tk * 2][b]  + sm->wsq[tk * 2 + 1][b];
            float m   = S * (1.f / POOL_);
            float var = Q * (1.f / POOL_) - m * m;
            float r   = rsqrtf(var + 1e-5f);
            yv[b] = (vv[b] - m) * r * gp + bp;
            ysum += yv[b];
        }
    }
    *ysum_out = ysum;
}

// ---------------------------------------------------------------------------
// Kernel A: y rows for t<64 only. grid = 32, block = 256.
// ---------------------------------------------------------------------------
__global__ __launch_bounds__(256, 4) void kA_yrows(
        const float* __restrict__ x,  const float* __restrict__ w1,
        const float* __restrict__ b1, const float* __restrict__ g1,
        const float* __restrict__ bt1) {
    __shared__ K1Smem sm;
    const int t0  = blockIdx.x * TK_;
    const int tid = threadIdx.x;
    float yv[B_]; float ysum;
    stage1_gemm_ln(&sm, t0, tid, x, w1, b1, g1, bt1, yv, &ysum);
    if (tid < TK_ * POOL_) {
        const int tk = tid >> 6, pp = tid & 63, t = t0 + tk;
        #pragma unroll
        for (int b = 0; b < B_; b++)
            g_y[(b * POOL_ + t) * POOL_ + pp] = yv[b];
    }
}

// ---------------------------------------------------------------------------
// Kernel 2: z[b,j,:] = LN(relu(y[b,j,:] @ w2 + b2))   (256 distinct rows)
// ---------------------------------------------------------------------------
__global__ void k2_expand(const float* __restrict__ w2,
                          const float* __restrict__ b2,
                          const float* __restrict__ g2,
                          const float* __restrict__ bt2) {
    const int bj = blockIdx.x;
    const int d  = threadIdx.x;

    __shared__ float yr[POOL_];
    if (d < POOL_) yr[d] = g_y[bj * POOL_ + d];
    __syncthreads();

    float acc = b2[d];
    #pragma unroll
    for (int p = 0; p < POOL_; p++)
        acc += yr[p] * w2[p * DIM_ + d];

    float v = fmaxf(acc, 0.f);

    float s = v, q = v * v;
    #pragma unroll
    for (int off = 16; off > 0; off >>= 1) {
        s += __shfl_xor_sync(0xffffffffu, s, off);
        q += __shfl_xor_sync(0xffffffffu, q, off);
    }
    __shared__ float ps[16], pq[16];
    const int w = d >> 5;
    if ((d & 31) == 0) { ps[w] = s; pq[w] = q; }
    __syncthreads();
    float S = 0.f, Q = 0.f;
    #pragma unroll
    for (int i = 0; i < 16; i++) { S += ps[i]; Q += pq[i]; }

    float m   = S * (1.f / DIM_);
    float var = Q * (1.f / DIM_) - m * m;
    g_z[bj * DIM_ + d] = (v - m) * rsqrtf(var + 1e-5f) * g2[d] + bt2[d];
}

// ---------------------------------------------------------------------------
// Kernel C (fused): per token pair — GEMM+LN+topk (idx in smem), then
// gather-write out[b,t,k,:] = z[b, idx[t,k], :] for its own 2 tokens.
// grid = 512, block = 256. The GEMM hides under the 419 MB write stream.
// ---------------------------------------------------------------------------
__global__ __launch_bounds__(256, 4) void kC_fused(
        const float* __restrict__ x,  const float* __restrict__ w1,
        const float* __restrict__ b1, const float* __restrict__ g1,
        const float* __restrict__ bt1,
        float* __restrict__ out) {
    __shared__ K1Smem sm;
    const int t0  = blockIdx.x * TK_;
    const int tid = threadIdx.x;

    float yv[B_]; float ysum;
    stage1_gemm_ln(&sm, t0, tid, x, w1, b1, g1, bt1, yv, &ysum);

    // stable top-50 of 64 per token
    if (tid < TK_ * POOL_) {
        const int tk = tid >> 6, pp = tid & 63;
        sm.sv[tk * POOL_ + pp] = ysum;
    }
    __syncthreads();
    if (tid < TK_ * POOL_) {
        const int tk = tid >> 6, pp = tid & 63;
        const float mine = sm.sv[tk * POOL_ + pp];
        int rank = 0;
        #pragma unroll
        for (int j = 0; j < POOL_; j++) {
            float o = sm.sv[tk * POOL_ + j];
            rank += (o > mine) || ((o == mine) && (j < pp));
        }
        if (rank < K_) sm.sidx[tk][rank] = pp;
    }
    __syncthreads();

    // gather-write: 2 tokens x 4 batches x 50 k rows of 512 floats (800KB)
    const int warp = tid >> 5;
    const int lane = tid & 31;
    for (int rr = warp; rr < TK_ * B_ * K_; rr += 8) {   // 400 rows, 50/warp
        int tk  = rr / (B_ * K_);
        int rem = rr - tk * (B_ * K_);
        int b   = rem / K_;
        int k   = rem - b * K_;
        int t   = t0 + tk;
        int j   = sm.sidx[tk][k];

        const float4* src = reinterpret_cast<const float4*>(g_z)
                            + (size_t)(b * POOL_ + j) * (DIM_ / 4);
        float4* dst = reinterpret_cast<float4*>(out)
                      + ((size_t)((b * T_ + t) * K_) + k) * (DIM_ / 4);
        #pragma unroll
        for (int cc = 0; cc < 4; cc++) {
            float4 v = __ldg(src + lane + 32 * cc);
            __stcs(dst + lane + 32 * cc, v);
        }
    }
}

// ---------------------------------------------------------------------------
extern "C" void kernel_launch(void* const* d_in, const int* in_sizes, int n_in,
                              void* d_out, int out_size) {
    const float* x   = (const float*)d_in[0];
    const float* w1  = (const float*)d_in[1];
    const float* b1  = (const float*)d_in[2];
    const float* g1  = (const float*)d_in[3];
    const float* bt1 = (const float*)d_in[4];
    const float* w2  = (const float*)d_in[5];
    const float* b2  = (const float*)d_in[6];
    const float* g2  = (const float*)d_in[7];
    const float* bt2 = (const float*)d_in[8];
    float* out = (float*)d_out;

    kA_yrows<<<POOL_ / TK_, 256>>>(x, w1, b1, g1, bt1);
    k2_expand<<<B_ * POOL_, DIM_>>>(w2, b2, g2, bt2);
    kC_fused<<<T_ / TK_, 256>>>(x, w1, b1, g1, bt1, out);
}

// round 9
// speedup vs baseline: 1.1284x; 1.1284x over previous
#include <cuda_runtime.h>
#include <cstdint>

#define B_    4
#define T_    1024
#define DIM_  512
#define POOL_ 64
#define K_    50
#define TK_   2      // tokens per k1 block

// Scratch (device globals: allocation-free per harness rules)
__device__ __align__(16) float g_y[B_ * POOL_ * POOL_];   // y[b][t<64][p]
__device__ int   g_idx[T_ * K_];                          // top-50 indices per t
__device__ __align__(16) float g_z[B_ * POOL_ * DIM_];    // z[b][j][d]

// packed fp32x2 ops (Blackwell FFMA2 — only reachable via PTX)
#define FMA2(d, a, b) \
    asm("fma.rn.f32x2 %0, %1, %2, %3;" : "=l"(d) : "l"(a), "l"(b), "l"(d))
#define ADD2(d, a, b) \
    asm("add.rn.f32x2 %0, %1, %2;" : "=l"(d) : "l"(a), "l"(b))
#define UNPACK2(lo, hi, v) \
    asm("mov.b64 {%0, %1}, %2;" : "=f"(lo), "=f"(hi) : "l"(v))
#define LDS_V2U64(a0, a1, addr) \
    asm("ld.shared.v2.b64 {%0, %1}, [%2];" : "=l"(a0), "=l"(a1) : "r"(addr))

// ---------------------------------------------------------------------------
// Kernel 1: 2 tokens/block, grid=512, block=256.
// f32x2 lanes = POOL PAIRS. Register blocking bt4 x pr4:
//   pg = tid&7   -> pools pg*8 .. pg*8+7 (4 pairs)
//   s  = (tid>>3)&1 -> (b,tok) rows s*4 .. s*4+3
//   dc = tid>>4  -> dims dc*32 .. dc*32+31
// Each LDS.128 (one x row, dims d,d+1 duplicated) feeds 8 FMA2.
// Butterfly over dc-pairs + smem reduce, LN + stable top-50 tail.
// ---------------------------------------------------------------------------
__global__ __launch_bounds__(256) void k1_reduce_topk(
        const float* __restrict__ x,
        const float* __restrict__ w1,
        const float* __restrict__ b1,
        const float* __restrict__ g1,
        const float* __restrict__ bt1) {
    // pool2: phase 1 = duplicated x, float2[(b*2+tok)*512 + d]  (32KB)
    //        phase 2 (reuse) = partials float[warp][bt][64]     (16KB)
    __shared__ __align__(16) float2 pool2[B_ * TK_ * DIM_];
    __shared__ float sv[TK_ * POOL_];
    __shared__ float wsum[4][B_], wsq[4][B_];
    float* poolf = reinterpret_cast<float*>(pool2);

    const int t0  = blockIdx.x * TK_;
    const int tid = threadIdx.x;
    const int pg  = tid & 7;          // pool group: pools pg*8 .. pg*8+7
    const int s   = (tid >> 3) & 1;   // row half: bt rows s*4 .. s*4+3
    const int dc  = tid >> 4;         // dim chunk: dims dc*32 .. dc*32+31

    uint32_t sx;
    asm("{ .reg .u64 t; cvta.to.shared.u64 t, %1; cvt.u32.u64 %0, t; }"
        : "=r"(sx) : "l"(pool2));

    // ---- phase 1: load x rows, lane-duplicated ----
    #pragma unroll
    for (int i = tid; i < B_ * (DIM_ / 4); i += 256) {
        int b = i >> 7, j = i & 127;
        const float* xb = x + ((size_t)b * T_ + t0) * DIM_;
        float4 v0 = reinterpret_cast<const float4*>(xb)[j];
        float4 v1 = reinterpret_cast<const float4*>(xb + DIM_)[j];
        float2* d0 = pool2 + (b * 2 + 0) * DIM_ + j * 4;
        d0[0] = make_float2(v0.x, v0.x);
        d0[1] = make_float2(v0.y, v0.y);
        d0[2] = make_float2(v0.z, v0.z);
        d0[3] = make_float2(v0.w, v0.w);
        float2* d1 = pool2 + (b * 2 + 1) * DIM_ + j * 4;
        d1[0] = make_float2(v1.x, v1.x);
        d1[1] = make_float2(v1.y, v1.y);
        d1[2] = make_float2(v1.z, v1.z);
        d1[3] = make_float2(v1.w, v1.w);
    }
    __syncthreads();

    // ---- main loop: 32 dims x 4 bt rows x 4 pool-pairs ----
    unsigned long long acc[4][4] = {};   // [row r][pair pr]
    const ulonglong2* w1q = reinterpret_cast<const ulonglong2*>(w1);
    // row d of w1 = 16 ulonglong2 (32 pool-pairs); thread takes 2pg, 2pg+1

    #pragma unroll 4
    for (int d2 = 0; d2 < 16; d2++) {
        const int d = dc * 32 + d2 * 2;
        ulonglong2 wa0 = __ldg(w1q + (size_t)d * 16 + 2 * pg);        // dim d,   pairs 4pg..4pg+1
        ulonglong2 wa1 = __ldg(w1q + (size_t)d * 16 + 2 * pg + 1);    // dim d,   pairs 4pg+2..3
        ulonglong2 wb0 = __ldg(w1q + (size_t)(d + 1) * 16 + 2 * pg);  // dim d+1
        ulonglong2 wb1 = __ldg(w1q + (size_t)(d + 1) * 16 + 2 * pg + 1);

        #pragma unroll
        for (int r = 0; r < 4; r++) {
            const int bt = s * 4 + r;
            unsigned long long xv0, xv1;   // dup x for dims d, d+1
            LDS_V2U64(xv0, xv1, sx + (uint32_t)((bt * DIM_ + d) * 8));
            FMA2(acc[r][0], xv0, wa0.x);
            FMA2(acc[r][1], xv0, wa0.y);
            FMA2(acc[r][2], xv0, wa1.x);
            FMA2(acc[r][3], xv0, wa1.y);
            FMA2(acc[r][0], xv1, wb0.x);
            FMA2(acc[r][1], xv1, wb0.y);
            FMA2(acc[r][2], xv1, wb1.x);
            FMA2(acc[r][3], xv1, wb1.y);
        }
    }

    // ---- reduce over dc: butterfly (dc pairs: tid bit 4), then smem ----
    #pragma unroll
    for (int r = 0; r < 4; r++) {
        #pragma unroll
        for (int pr = 0; pr < 4; pr++) {
            unsigned long long o = __shfl_xor_sync(0xffffffffu, acc[r][pr], 16);
            ADD2(acc[r][pr], acc[r][pr], o);
        }
    }
    __syncthreads();   // all x reads done; reuse poolf for partials

    if ((tid & 16) == 0) {          // dc-even lane per (warp, pg, s)
        const int w = tid >> 5;     // 0..7
        #pragma unroll
        for (int r = 0; r < 4; r++) {
            const int bt = s * 4 + r;
            #pragma unroll
            for (int pr = 0; pr < 4; pr++) {
                float lo, hi;                  // pools pg*8 + pr*2, +1
                UNPACK2(lo, hi, acc[r][pr]);
                poolf[w * 512 + bt * 64 + pg * 8 + pr * 2 + 0] = lo;
                poolf[w * 512 + bt * 64 + pg * 8 + pr * 2 + 1] = hi;
            }
        }
    }
    __syncthreads();

    // ---- tail on first 128 threads: tk = tid>>6, pp = tid&63 ----
    float vv[B_];
    if (tid < TK_ * POOL_) {
        const int tk = tid >> 6;
        const int pp = tid & 63;
        const float bias = b1[pp];

        #pragma unroll
        for (int b = 0; b < B_; b++) {
            float a = bias;
            #pragma unroll
            for (int w = 0; w < 8; w++)
                a += poolf[w * 512 + (b * TK_ + tk) * 64 + pp];
            vv[b] = fmaxf(a, 0.f);
        }

        float ss[B_], qq[B_];
        #pragma unroll
        for (int b = 0; b < B_; b++) { ss[b] = vv[b]; qq[b] = vv[b] * vv[b]; }
        #pragma unroll
        for (int off = 16; off > 0; off >>= 1) {
            #pragma unroll
            for (int b = 0; b < B_; b++) {
                ss[b] += __shfl_xor_sync(0xffffffffu, ss[b], off);
                qq[b] += __shfl_xor_sync(0xffffffffu, qq[b], off);
            }
        }
        const int w = tid >> 5;   // warps 0..3 (2 per token)
        if ((tid & 31) == 0) {
            #pragma unroll
            for (int b = 0; b < B_; b++) { wsum[w][b] = ss[b]; wsq[w][b] = qq[b]; }
        }
    }
    __syncthreads();

    if (tid < TK_ * POOL_) {
        const int tk = tid >> 6;
        const int pp = tid & 63;
        const int t  = t0 + tk;
        const float gp = g1[pp], bp = bt1[pp];

        float ysum = 0.f;
        float yv[B_];
        #pragma unroll
        for (int b = 0; b < B_; b++) {
            float S = wsum[tk * 2][b] + wsum[tk * 2 + 1][b];
            float Q = wsq[tk * 2][b]  + wsq[tk * 2 + 1][b];
            float m   = S * (1.f / POOL_);
            float var = Q * (1.f / POOL_) - m * m;
            float r   = rsqrtf(var + 1e-5f);
            yv[b] = (vv[b] - m) * r * gp + bp;
            ysum += yv[b];
        }

        if (t < POOL_) {
            #pragma unroll
            for (int b = 0; b < B_; b++)
                g_y[(b * POOL_ + t) * POOL_ + pp] = yv[b];
        }

        sv[tk * POOL_ + pp] = ysum;
        __syncwarp();
        asm volatile("bar.sync 1, 128;" ::: "memory");

        const float mine = ysum;
        int rank = 0;
        #pragma unroll
        for (int j = 0; j < POOL_; j++) {
            float o = sv[tk * POOL_ + j];
            rank += (o > mine) || ((o == mine) && (j < pp));
        }
        if (rank < K_) g_idx[t * K_ + rank] = pp;
    }
}

// ---------------------------------------------------------------------------
// Kernel 2: z[b,j,:] = LN(relu(y[b,j,:] @ w2 + b2))   (256 distinct rows)
// grid = B_*POOL_, block = 512
// ---------------------------------------------------------------------------
__global__ void k2_expand(const float* __restrict__ w2,
                          const float* __restrict__ b2,
                          const float* __restrict__ g2,
                          const float* __restrict__ bt2) {
    const int bj = blockIdx.x;
    const int d  = threadIdx.x;

    __shared__ float yr[POOL_];
    if (d < POOL_) yr[d] = g_y[bj * POOL_ + d];
    __syncthreads();

    float acc = b2[d];
    #pragma unroll
    for (int p = 0; p < POOL_; p++)
        acc += yr[p] * w2[p * DIM_ + d];

    float v = fmaxf(acc, 0.f);

    float s = v, q = v * v;
    #pragma unroll
    for (int off = 16; off > 0; off >>= 1) {
        s += __shfl_xor_sync(0xffffffffu, s, off);
        q += __shfl_xor_sync(0xffffffffu, q, off);
    }
    __shared__ float ps[16], pq[16];
    const int w = d >> 5;
    if ((d & 31) == 0) { ps[w] = s; pq[w] = q; }
    __syncthreads();
    float S = 0.f, Q = 0.f;
    #pragma unroll
    for (int i = 0; i < 16; i++) { S += ps[i]; Q += pq[i]; }

    float m   = S * (1.f / DIM_);
    float var = Q * (1.f / DIM_) - m * m;
    g_z[bj * DIM_ + d] = (v - m) * rsqrtf(var + 1e-5f) * g2[d] + bt2[d];
}

// ---------------------------------------------------------------------------
// Kernel 3: out[b,t,k,:] = z[b, idx[t,k], :]  — the 419 MB write stream.
// At the HBM-write roofline. Unchanged from the best configuration.
// ---------------------------------------------------------------------------
__global__ void k3_gather(float* __restrict__ out) {
    const int warp = threadIdx.x >> 5;
    const int lane = threadIdx.x & 31;
    const unsigned base = blockIdx.x * 64u;

    #pragma unroll
    for (int i = 0; i < 4; i++) {
        unsigned r   = base + warp + i * 16;
        unsigned b   = r / (unsigned)(T_ * K_);
        unsigned rem = r - b * (unsigned)(T_ * K_);
        unsigned t   = rem / K_;
        unsigned k   = rem - t * K_;
        int j = g_idx[t * K_ + k];

        const float4* src = reinterpret_cast<const float4*>(g_z)
                            + (size_t)(b * POOL_ + j) * (DIM_ / 4);
        float4* dst = reinterpret_cast<float4*>(out)
                      + (size_t)r * (DIM_ / 4);
        #pragma unroll
        for (int cc = 0; cc < 4; cc++) {
            float4 v = __ldg(src + lane + 32 * cc);
            __stcs(dst + lane + 32 * cc, v);
        }
    }
}

// ---------------------------------------------------------------------------
extern "C" void kernel_launch(void* const* d_in, const int* in_sizes, int n_in,
                              void* d_out, int out_size) {
    const float* x   = (const float*)d_in[0];
    const float* w1  = (const float*)d_in[1];
    const float* b1  = (const float*)d_in[2];
    const float* g1  = (const float*)d_in[3];
    const float* bt1 = (const float*)d_in[4];
    const float* w2  = (const float*)d_in[5];
    const float* b2  = (const float*)d_in[6];
    const float* g2  = (const float*)d_in[7];
    const float* bt2 = (const float*)d_in[8];
    float* out = (float*)d_out;

    k1_reduce_topk<<<T_ / TK_, 256>>>(x, w1, b1, g1, bt1);
    k2_expand<<<B_ * POOL_, DIM_>>>(w2, b2, g2, bt2);
    k3_gather<<<(B_ * T_ * K_) / 64, 512>>>(out);
}

// round 10
// speedup vs baseline: 1.1826x; 1.0480x over previous
#include <cuda_runtime.h>
#include <cstdint>

#define B_    4
#define T_    1024
#define DIM_  512
#define POOL_ 64
#define K_    50
#define TK_   2      // tokens per k1 block

#define T_SPLIT 576  // k1a/k3a handle tokens [0,576), k1b/k3b [576,1024)

// Scratch (device globals: allocation-free per harness rules)
__device__ __align__(16) float g_y[B_ * POOL_ * POOL_];   // y[b][t<64][p]
__device__ int   g_idx[T_ * K_];                          // top-50 indices per t
__device__ __align__(16) float g_z[B_ * POOL_ * DIM_];    // z[b][j][d]

// packed fp32x2 ops (Blackwell FFMA2 — only reachable via PTX)
#define FMA2(d, a, b) \
    asm("fma.rn.f32x2 %0, %1, %2, %3;" : "=l"(d) : "l"(a), "l"(b), "l"(d))
#define ADD2(d, a, b) \
    asm("add.rn.f32x2 %0, %1, %2;" : "=l"(d) : "l"(a), "l"(b))
#define UNPACK2(lo, hi, v) \
    asm("mov.b64 {%0, %1}, %2;" : "=f"(lo), "=f"(hi) : "l"(v))
#define LDS_V2U64(a0, a1, addr) \
    asm("ld.shared.v2.b64 {%0, %1}, [%2];" : "=l"(a0), "=l"(a1) : "r"(addr))

// ---------------------------------------------------------------------------
// Kernel 1 (round-5 best config): 2 tokens/block, block=256.
// f32x2 lanes = POOL PAIRS; x staged lane-duplicated in smem.
// Thread (dc=tid>>4, pg=tid&15): pools pg*4..pg*4+3, 8 (b,tok) rows,
// dims [dc*32, dc*32+32). Butterfly + smem reduce, LN + stable top-50.
// t_off selects the token range.
// ---------------------------------------------------------------------------
__global__ __launch_bounds__(256) void k1_reduce_topk(
        const float* __restrict__ x,
        const float* __restrict__ w1,
        const float* __restrict__ b1,
        const float* __restrict__ g1,
        const float* __restrict__ bt1,
        int t_off) {
    __shared__ __align__(16) float2 pool2[B_ * TK_ * DIM_];  // 32KB
    __shared__ float sv[TK_ * POOL_];
    __shared__ float wsum[4][B_], wsq[4][B_];
    float* poolf = reinterpret_cast<float*>(pool2);

    const int t0  = t_off + blockIdx.x * TK_;
    const int tid = threadIdx.x;
    const int pg  = tid & 15;
    const int dc  = tid >> 4;

    uint32_t sx;
    asm("{ .reg .u64 t; cvta.to.shared.u64 t, %1; cvt.u32.u64 %0, t; }"
        : "=r"(sx) : "l"(pool2));

    // ---- phase 1: load x rows, lane-duplicated ----
    #pragma unroll
    for (int i = tid; i < B_ * (DIM_ / 4); i += 256) {
        int b = i >> 7, j = i & 127;
        const float* xb = x + ((size_t)b * T_ + t0) * DIM_;
        float4 v0 = reinterpret_cast<const float4*>(xb)[j];
        float4 v1 = reinterpret_cast<const float4*>(xb + DIM_)[j];
        float2* d0 = pool2 + (b * 2 + 0) * DIM_ + j * 4;
        d0[0] = make_float2(v0.x, v0.x);
        d0[1] = make_float2(v0.y, v0.y);
        d0[2] = make_float2(v0.z, v0.z);
        d0[3] = make_float2(v0.w, v0.w);
        float2* d1 = pool2 + (b * 2 + 1) * DIM_ + j * 4;
        d1[0] = make_float2(v1.x, v1.x);
        d1[1] = make_float2(v1.y, v1.y);
        d1[2] = make_float2(v1.z, v1.z);
        d1[3] = make_float2(v1.w, v1.w);
    }
    __syncthreads();

    // ---- main loop: 32 dims x 8 (b,tok) rows x 2 pool-pairs ----
    unsigned long long acc[8][2] = {};
    const ulonglong2* w1q = reinterpret_cast<const ulonglong2*>(w1);

    #pragma unroll 4
    for (int d2 = 0; d2 < 16; d2++) {
        const int d = dc * 32 + d2 * 2;
        ulonglong2 wd0 = __ldg(w1q + (size_t)d * 16 + pg);
        ulonglong2 wd1 = __ldg(w1q + (size_t)(d + 1) * 16 + pg);
        #pragma unroll
        for (int bt = 0; bt < 8; bt++) {
            unsigned long long xv0, xv1;
            LDS_V2U64(xv0, xv1, sx + (uint32_t)((bt * DIM_ + d) * 8));
            FMA2(acc[bt][0], xv0, wd0.x);
            FMA2(acc[bt][1], xv0, wd0.y);
            FMA2(acc[bt][0], xv1, wd1.x);
            FMA2(acc[bt][1], xv1, wd1.y);
        }
    }

    // ---- reduce over dc: butterfly (dc pairs), then smem ----
    #pragma unroll
    for (int bt = 0; bt < 8; bt++) {
        #pragma unroll
        for (int pr = 0; pr < 2; pr++) {
            unsigned long long o = __shfl_xor_sync(0xffffffffu, acc[bt][pr], 16);
            ADD2(acc[bt][pr], acc[bt][pr], o);
        }
    }
    __syncthreads();

    if ((tid & 16) == 0) {
        const int w = tid >> 5;
        #pragma unroll
        for (int bt = 0; bt < 8; bt++) {
            #pragma unroll
            for (int pr = 0; pr < 2; pr++) {
                float lo, hi;
                UNPACK2(lo, hi, acc[bt][pr]);
                poolf[w * 512 + bt * 64 + pg * 4 + pr * 2 + 0] = lo;
                poolf[w * 512 + bt * 64 + pg * 4 + pr * 2 + 1] = hi;
            }
        }
    }
    __syncthreads();

    // ---- tail on first 128 threads: tk = tid>>6, pp = tid&63 ----
    float vv[B_];
    if (tid < TK_ * POOL_) {
        const int tk = tid >> 6;
        const int pp = tid & 63;
        const float bias = b1[pp];
        #pragma unroll
        for (int b = 0; b < B_; b++) {
            float a = bias;
            #pragma unroll
            for (int w = 0; w < 8; w++)
                a += poolf[w * 512 + (b * TK_ + tk) * 64 + pp];
            vv[b] = fmaxf(a, 0.f);
        }
        float s[B_], q[B_];
        #pragma unroll
        for (int b = 0; b < B_; b++) { s[b] = vv[b]; q[b] = vv[b] * vv[b]; }
        #pragma unroll
        for (int off = 16; off > 0; off >>= 1) {
            #pragma unroll
            for (int b = 0; b < B_; b++) {
                s[b] += __shfl_xor_sync(0xffffffffu, s[b], off);
                q[b] += __shfl_xor_sync(0xffffffffu, q[b], off);
            }
        }
        const int w = tid >> 5;
        if ((tid & 31) == 0) {
            #pragma unroll
            for (int b = 0; b < B_; b++) { wsum[w][b] = s[b]; wsq[w][b] = q[b]; }
        }
    }
    __syncthreads();

    if (tid < TK_ * POOL_) {
        const int tk = tid >> 6;
        const int pp = tid & 63;
        const int t  = t0 + tk;
        const float gp = g1[pp], bp = bt1[pp];

        float ysum = 0.f;
        float yv[B_];
        #pragma unroll
        for (int b = 0; b < B_; b++) {
            float S = wsum[tk * 2][b] + wsum[tk * 2 + 1][b];
            float Q = wsq[tk * 2][b]  + wsq[tk * 2 + 1][b];
            float m   = S * (1.f / POOL_);
            float var = Q * (1.f / POOL_) - m * m;
            float r   = rsqrtf(var + 1e-5f);
            yv[b] = (vv[b] - m) * r * gp + bp;
            ysum += yv[b];
        }

        if (t < POOL_) {
            #pragma unroll
            for (int b = 0; b < B_; b++)
                g_y[(b * POOL_ + t) * POOL_ + pp] = yv[b];
        }

        sv[tk * POOL_ + pp] = ysum;
        __syncwarp();
        asm volatile("bar.sync 1, 128;" ::: "memory");

        const float mine = ysum;
        int rank = 0;
        #pragma unroll
        for (int j = 0; j < POOL_; j++) {
            float o = sv[tk * POOL_ + j];
            rank += (o > mine) || ((o == mine) && (j < pp));
        }
        if (rank < K_) g_idx[t * K_ + rank] = pp;
    }
}

// ---------------------------------------------------------------------------
// Kernel 2: z[b,j,:] = LN(relu(y[b,j,:] @ w2 + b2))   (256 distinct rows)
// ---------------------------------------------------------------------------
__global__ void k2_expand(const float* __restrict__ w2,
                          const float* __restrict__ b2,
                          const float* __restrict__ g2,
                          const float* __restrict__ bt2) {
    const int bj = blockIdx.x;
    const int d  = threadIdx.x;

    __shared__ float yr[POOL_];
    if (d < POOL_) yr[d] = g_y[bj * POOL_ + d];
    __syncthreads();

    float acc = b2[d];
    #pragma unroll
    for (int p = 0; p < POOL_; p++)
        acc += yr[p] * w2[p * DIM_ + d];

    float v = fmaxf(acc, 0.f);

    float s = v, q = v * v;
    #pragma unroll
    for (int off = 16; off > 0; off >>= 1) {
        s += __shfl_xor_sync(0xffffffffu, s, off);
        q += __shfl_xor_sync(0xffffffffu, q, off);
    }
    __shared__ float ps[16], pq[16];
    const int w = d >> 5;
    if ((d & 31) == 0) { ps[w] = s; pq[w] = q; }
    __syncthreads();
    float S = 0.f, Q = 0.f;
    #pragma unroll
    for (int i = 0; i < 16; i++) { S += ps[i]; Q += pq[i]; }

    float m   = S * (1.f / DIM_);
    float var = Q * (1.f / DIM_) - m * m;
    g_z[bj * DIM_ + d] = (v - m) * rsqrtf(var + 1e-5f) * g2[d] + bt2[d];
}

// ---------------------------------------------------------------------------
// Kernel 3: out[b,t,k,:] = z[b, idx[t,k], :] for tokens [t_lo, t_lo+n_tok).
// Warp-per-row float4 copies; z via __ldg (L2-hot), output via __stcs.
// grid = n_tok*B_*K_/64, block = 512 (64 rows/block).
// ---------------------------------------------------------------------------
__global__ void k3_gather(float* __restrict__ out, int t_lo) {
    const int warp = threadIdx.x >> 5;
    const int lane = threadIdx.x & 31;
    const unsigned base = blockIdx.x * 64u;

    #pragma unroll
    for (int i = 0; i < 4; i++) {
        unsigned rr  = base + warp + i * 16;         // local row
        unsigned tt  = rr / (unsigned)(B_ * K_);     // local token
        unsigned rem = rr - tt * (unsigned)(B_ * K_);
        unsigned b   = rem / K_;
        unsigned k   = rem - b * K_;
        unsigned t   = t_lo + tt;
        int j = g_idx[t * K_ + k];

        const float4* src = reinterpret_cast<const float4*>(g_z)
                            + (size_t)(b * POOL_ + j) * (DIM_ / 4);
        float4* dst = reinterpret_cast<float4*>(out)
                      + ((size_t)((b * T_ + t) * K_) + k) * (DIM_ / 4);
        #pragma unroll
        for (int cc = 0; cc < 4; cc++) {
            float4 v = __ldg(src + lane + 32 * cc);
            __stcs(dst + lane + 32 * cc, v);
        }
    }
}

// ---------------------------------------------------------------------------
// Fork/join resources — created once at load time (host-side; no device
// memory allocation involved).
// ---------------------------------------------------------------------------
namespace {
cudaStream_t g_s2 = nullptr;
cudaEvent_t  g_e1 = nullptr, g_e2 = nullptr;
struct StreamInit {
    StreamInit() {
        if (cudaStreamCreateWithFlags(&g_s2, cudaStreamNonBlocking) != cudaSuccess)
            g_s2 = nullptr;
        if (cudaEventCreateWithFlags(&g_e1, cudaEventDisableTiming) != cudaSuccess)
            g_e1 = nullptr;
        if (cudaEventCreateWithFlags(&g_e2, cudaEventDisableTiming) != cudaSuccess)
            g_e2 = nullptr;
    }
} g_stream_init;
}

// ---------------------------------------------------------------------------
extern "C" void kernel_launch(void* const* d_in, const int* in_sizes, int n_in,
                              void* d_out, int out_size) {
    const float* x   = (const float*)d_in[0];
    const float* w1  = (const float*)d_in[1];
    const float* b1  = (const float*)d_in[2];
    const float* g1  = (const float*)d_in[3];
    const float* bt1 = (const float*)d_in[4];
    const float* w2  = (const float*)d_in[5];
    const float* b2  = (const float*)d_in[6];
    const float* g2  = (const float*)d_in[7];
    const float* bt2 = (const float*)d_in[8];
    float* out = (float*)d_out;

    const int nA = T_SPLIT;          // tokens in first chunk
    const int nB = T_ - T_SPLIT;     // tokens in second chunk

    if (g_s2 && g_e1 && g_e2) {
        // k1a: tokens [0, 576) — includes all t<64 (g_y complete)
        k1_reduce_topk<<<nA / TK_, 256>>>(x, w1, b1, g1, bt1, 0);
        // k2: z rows (needs g_y)
        k2_expand<<<B_ * POOL_, DIM_>>>(w2, b2, g2, bt2);

        // fork: k1b on side stream, k3a on main stream — they overlap
        cudaEventRecord(g_e1, 0);
        cudaStreamWaitEvent(g_s2, g_e1, 0);
        k1_reduce_topk<<<nB / TK_, 256, 0, g_s2>>>(x, w1, b1, g1, bt1, T_SPLIT);
        cudaEventRecord(g_e2, g_s2);

        k3_gather<<<(nA * B_ * K_) / 64, 512>>>(out, 0);

        // join: k3b needs g_idx for tokens >= 576
        cudaStreamWaitEvent(0, g_e2, 0);
        k3_gather<<<(nB * B_ * K_) / 64, 512>>>(out, T_SPLIT);
    } else {
        // sequential fallback
        k1_reduce_topk<<<T_ / TK_, 256>>>(x, w1, b1, g1, bt1, 0);
        k2_expand<<<B_ * POOL_, DIM_>>>(w2, b2, g2, bt2);
        k3_gather<<<(T_ * B_ * K_) / 64, 512>>>(out, 0);
    }
}

// round 11
// speedup vs baseline: 1.2239x; 1.0349x over previous
#include <cuda_runtime.h>
#include <cstdint>

#define B_    4
#define T_    1024
#define DIM_  512
#define POOL_ 64
#define K_    50
#define TK_   2      // tokens per k1 block

// Scratch (device globals: allocation-free per harness rules)
__device__ __align__(16) float g_y[B_ * POOL_ * POOL_];   // y[b][t<64][p]
__device__ int   g_idx[T_ * K_];                          // top-50 indices per t
__device__ __align__(16) float g_z[B_ * POOL_ * DIM_];    // z[b][j][d]

// packed fp32x2 ops (Blackwell FFMA2 — only reachable via PTX)
#define FMA2(d, a, b) \
    asm("fma.rn.f32x2 %0, %1, %2, %3;" : "=l"(d) : "l"(a), "l"(b), "l"(d))
#define ADD2(d, a, b) \
    asm("add.rn.f32x2 %0, %1, %2;" : "=l"(d) : "l"(a), "l"(b))
#define UNPACK2(lo, hi, v) \
    asm("mov.b64 {%0, %1}, %2;" : "=f"(lo), "=f"(hi) : "l"(v))
#define LDS_V2U64(a0, a1, addr) \
    asm("ld.shared.v2.b64 {%0, %1}, [%2];" : "=l"(a0), "=l"(a1) : "r"(addr))

// ---------------------------------------------------------------------------
// Kernel 1: 2 tokens/block, grid=512, block=256 (round-5 layout).
// f32x2 lanes = POOL PAIRS; x staged lane-duplicated in smem.
// Thread (dc=tid>>4, pg=tid&15): pools pg*4..pg*4+3, 8 (b,tok) rows,
// dims [dc*32, dc*32+32).
// NEW: software-pipelined w1 loads (prefetch d2+1 while computing d2) and
// LDS batched 4-at-a-time ahead of their FMA2 groups.
// ---------------------------------------------------------------------------
__global__ __launch_bounds__(256, 3) void k1_reduce_topk(
        const float* __restrict__ x,
        const float* __restrict__ w1,
        const float* __restrict__ b1,
        const float* __restrict__ g1,
        const float* __restrict__ bt1) {
    __shared__ __align__(16) float2 pool2[B_ * TK_ * DIM_];  // 32KB
    __shared__ float sv[TK_ * POOL_];
    __shared__ float wsum[4][B_], wsq[4][B_];
    float* poolf = reinterpret_cast<float*>(pool2);

    const int t0  = blockIdx.x * TK_;
    const int tid = threadIdx.x;
    const int pg  = tid & 15;
    const int dc  = tid >> 4;

    uint32_t sx;
    asm("{ .reg .u64 t; cvta.to.shared.u64 t, %1; cvt.u32.u64 %0, t; }"
        : "=r"(sx) : "l"(pool2));

    // ---- phase 1: load x rows, lane-duplicated ----
    #pragma unroll
    for (int i = tid; i < B_ * (DIM_ / 4); i += 256) {
        int b = i >> 7, j = i & 127;
        const float* xb = x + ((size_t)b * T_ + t0) * DIM_;
        float4 v0 = reinterpret_cast<const float4*>(xb)[j];
        float4 v1 = reinterpret_cast<const float4*>(xb + DIM_)[j];
        float2* d0 = pool2 + (b * 2 + 0) * DIM_ + j * 4;
        d0[0] = make_float2(v0.x, v0.x);
        d0[1] = make_float2(v0.y, v0.y);
        d0[2] = make_float2(v0.z, v0.z);
        d0[3] = make_float2(v0.w, v0.w);
        float2* d1 = pool2 + (b * 2 + 1) * DIM_ + j * 4;
        d1[0] = make_float2(v1.x, v1.x);
        d1[1] = make_float2(v1.y, v1.y);
        d1[2] = make_float2(v1.z, v1.z);
        d1[3] = make_float2(v1.w, v1.w);
    }
    __syncthreads();

    // ---- main loop: software-pipelined over d2 ----
    unsigned long long acc[8][2] = {};
    const ulonglong2* wp = reinterpret_cast<const ulonglong2*>(w1)
                           + (size_t)(dc * 32) * 16 + pg;   // dim row = 16 u64x2

    ulonglong2 wc0 = __ldg(wp);          // dims d, d+1 for d2 = 0
    ulonglong2 wc1 = __ldg(wp + 16);

    #pragma unroll
    for (int d2 = 0; d2 < 16; d2++) {
        const int d = dc * 32 + d2 * 2;
        // prefetch next iteration's weights (clamped; last load redundant L1 hit)
        const int nx = (d2 < 15) ? (d2 + 1) : 15;
        ulonglong2 wn0 = __ldg(wp + nx * 32);
        ulonglong2 wn1 = __ldg(wp + nx * 32 + 16);

        unsigned long long xv[8];
        // rows 0..3: batch LDS, then FMA
        #pragma unroll
        for (int r = 0; r < 4; r++)
            LDS_V2U64(xv[2 * r], xv[2 * r + 1],
                      sx + (uint32_t)((r * DIM_ + d) * 8));
        #pragma unroll
        for (int r = 0; r < 4; r++) {
            FMA2(acc[r][0], xv[2 * r],     wc0.x);
            FMA2(acc[r][1], xv[2 * r],     wc0.y);
            FMA2(acc[r][0], xv[2 * r + 1], wc1.x);
            FMA2(acc[r][1], xv[2 * r + 1], wc1.y);
        }
        // rows 4..7: batch LDS, then FMA
        #pragma unroll
        for (int r = 0; r < 4; r++)
            LDS_V2U64(xv[2 * r], xv[2 * r + 1],
                      sx + (uint32_t)(((r + 4) * DIM_ + d) * 8));
        #pragma unroll
        for (int r = 0; r < 4; r++) {
            FMA2(acc[r + 4][0], xv[2 * r],     wc0.x);
            FMA2(acc[r + 4][1], xv[2 * r],     wc0.y);
            FMA2(acc[r + 4][0], xv[2 * r + 1], wc1.x);
            FMA2(acc[r + 4][1], xv[2 * r + 1], wc1.y);
        }
        wc0 = wn0;
        wc1 = wn1;
    }

    // ---- reduce over dc: butterfly (dc pairs), then smem ----
    #pragma unroll
    for (int bt = 0; bt < 8; bt++) {
        #pragma unroll
        for (int pr = 0; pr < 2; pr++) {
            unsigned long long o = __shfl_xor_sync(0xffffffffu, acc[bt][pr], 16);
            ADD2(acc[bt][pr], acc[bt][pr], o);
        }
    }
    __syncthreads();   // all x reads done; reuse poolf for partials

    if ((tid & 16) == 0) {
        const int w = tid >> 5;
        #pragma unroll
        for (int bt = 0; bt < 8; bt++) {
            #pragma unroll
            for (int pr = 0; pr < 2; pr++) {
                float lo, hi;
                UNPACK2(lo, hi, acc[bt][pr]);
                poolf[w * 512 + bt * 64 + pg * 4 + pr * 2 + 0] = lo;
                poolf[w * 512 + bt * 64 + pg * 4 + pr * 2 + 1] = hi;
            }
        }
    }
    __syncthreads();

    // ---- tail on first 128 threads: tk = tid>>6, pp = tid&63 ----
    float vv[B_];
    if (tid < TK_ * POOL_) {
        const int tk = tid >> 6;
        const int pp = tid & 63;
        const float bias = b1[pp];
        #pragma unroll
        for (int b = 0; b < B_; b++) {
            float a = bias;
            #pragma unroll
            for (int w = 0; w < 8; w++)
                a += poolf[w * 512 + (b * TK_ + tk) * 64 + pp];
            vv[b] = fmaxf(a, 0.f);
        }
        float s[B_], q[B_];
        #pragma unroll
        for (int b = 0; b < B_; b++) { s[b] = vv[b]; q[b] = vv[b] * vv[b]; }
        #pragma unroll
        for (int off = 16; off > 0; off >>= 1) {
            #pragma unroll
            for (int b = 0; b < B_; b++) {
                s[b] += __shfl_xor_sync(0xffffffffu, s[b], off);
                q[b] += __shfl_xor_sync(0xffffffffu, q[b], off);
            }
        }
        const int w = tid >> 5;
        if ((tid & 31) == 0) {
            #pragma unroll
            for (int b = 0; b < B_; b++) { wsum[w][b] = s[b]; wsq[w][b] = q[b]; }
        }
    }
    __syncthreads();

    if (tid < TK_ * POOL_) {
        const int tk = tid >> 6;
        const int pp = tid & 63;
        const int t  = t0 + tk;
        const float gp = g1[pp], bp = bt1[pp];

        float ysum = 0.f;
        float yv[B_];
        #pragma unroll
        for (int b = 0; b < B_; b++) {
            float S = wsum[tk * 2][b] + wsum[tk * 2 + 1][b];
            float Q = wsq[tk * 2][b]  + wsq[tk * 2 + 1][b];
            float m   = S * (1.f / POOL_);
            float var = Q * (1.f / POOL_) - m * m;
            float r   = rsqrtf(var + 1e-5f);
            yv[b] = (vv[b] - m) * r * gp + bp;
            ysum += yv[b];
        }

        if (t < POOL_) {
            #pragma unroll
            for (int b = 0; b < B_; b++)
                g_y[(b * POOL_ + t) * POOL_ + pp] = yv[b];
        }

        sv[tk * POOL_ + pp] = ysum;
        __syncwarp();
        asm volatile("bar.sync 1, 128;" ::: "memory");

        const float mine = ysum;
        int rank = 0;
        #pragma unroll
        for (int j = 0; j < POOL_; j++) {
            float o = sv[tk * POOL_ + j];
            rank += (o > mine) || ((o == mine) && (j < pp));
        }
        if (rank < K_) g_idx[t * K_ + rank] = pp;
    }
}

// ---------------------------------------------------------------------------
// Kernel 2: z[b,j,:] = LN(relu(y[b,j,:] @ w2 + b2))   (256 distinct rows)
// ---------------------------------------------------------------------------
__global__ void k2_expand(const float* __restrict__ w2,
                          const float* __restrict__ b2,
                          const float* __restrict__ g2,
                          const float* __restrict__ bt2) {
    const int bj = blockIdx.x;
    const int d  = threadIdx.x;

    __shared__ float yr[POOL_];
    if (d < POOL_) yr[d] = g_y[bj * POOL_ + d];
    __syncthreads();

    float acc = b2[d];
    #pragma unroll
    for (int p = 0; p < POOL_; p++)
        acc += yr[p] * w2[p * DIM_ + d];

    float v = fmaxf(acc, 0.f);

    float s = v, q = v * v;
    #pragma unroll
    for (int off = 16; off > 0; off >>= 1) {
        s += __shfl_xor_sync(0xffffffffu, s, off);
        q += __shfl_xor_sync(0xffffffffu, q, off);
    }
    __shared__ float ps[16], pq[16];
    const int w = d >> 5;
    if ((d & 31) == 0) { ps[w] = s; pq[w] = q; }
    __syncthreads();
    float S = 0.f, Q = 0.f;
    #pragma unroll
    for (int i = 0; i < 16; i++) { S += ps[i]; Q += pq[i]; }

    float m   = S * (1.f / DIM_);
    float var = Q * (1.f / DIM_) - m * m;
    g_z[bj * DIM_ + d] = (v - m) * rsqrtf(var + 1e-5f) * g2[d] + bt2[d];
}

// ---------------------------------------------------------------------------
// Kernel 3: out[b,t,k,:] = z[b, idx[t,k], :]  — the 419 MB write stream.
// At the HBM-write roofline. Unchanged from the best configuration.
// ---------------------------------------------------------------------------
__global__ void k3_gather(float* __restrict__ out) {
    const int warp = threadIdx.x >> 5;
    const int lane = threadIdx.x & 31;
    const unsigned base = blockIdx.x * 64u;

    #pragma unroll
    for (int i = 0; i < 4; i++) {
        unsigned r   = base + warp + i * 16;
        unsigned b   = r / (unsigned)(T_ * K_);
        unsigned rem = r - b * (unsigned)(T_ * K_);
        unsigned t   = rem / K_;
        unsigned k   = rem - t * K_;
        int j = g_idx[t * K_ + k];

        const float4* src = reinterpret_cast<const float4*>(g_z)
                            + (size_t)(b * POOL_ + j) * (DIM_ / 4);
        float4* dst = reinterpret_cast<float4*>(out)
                      + (size_t)r * (DIM_ / 4);
        #pragma unroll
        for (int cc = 0; cc < 4; cc++) {
            float4 v = __ldg(src + lane + 32 * cc);
            __stcs(dst + lane + 32 * cc, v);
        }
    }
}

// ---------------------------------------------------------------------------
extern "C" void kernel_launch(void* const* d_in, const int* in_sizes, int n_in,
                              void* d_out, int out_size) {
    const float* x   = (const float*)d_in[0];
    const float* w1  = (const float*)d_in[1];
    const float* b1  = (const float*)d_in[2];
    const float* g1  = (const float*)d_in[3];
    const float* bt1 = (const float*)d_in[4];
    const float* w2  = (const float*)d_in[5];
    const float* b2  = (const float*)d_in[6];
    const float* g2  = (const float*)d_in[7];
    const float* bt2 = (const float*)d_in[8];
    float* out = (float*)d_out;

    k1_reduce_topk<<<T_ / TK_, 256>>>(x, w1, b1, g1, bt1);
    k2_expand<<<B_ * POOL_, DIM_>>>(w2, b2, g2, bt2);
    k3_gather<<<(B_ * T_ * K_) / 64, 512>>>(out);
}